// round 12
// baseline (speedup 1.0000x reference)
#include <cuda_runtime.h>
#include <cstdint>
#include <math.h>

#define D_MODEL     2048
#define NUM_EXPERTS 64
#define N_TOKENS    16384
#define BM          64                  // tokens per CTA
#define BK          32                  // K per chunk
#define NCHUNK      (D_MODEL / BK)      // 64
#define THREADS     192                 // 4 consumer warps + 2 producer warps
#define NSTAGE      3
#define ROWB        160                 // bytes per smem row (128 data + 32 pad)
#define GAP_THRESH  3e-4f
#define LSTRIDE     65

// stage: A tile 64x160 then B tile 64x160
#define SM_BIAS     0
#define SM_BUF      256
#define BOFF        (BM * ROWB)                   // 10240
#define STAGE       (2 * BOFF)                    // 20480
#define SM_FLAGS    (SM_BUF + 17024)              // after L[64][65] floats (16640)
#define SMEM_TOTAL  (SM_BUF + NSTAGE * STAGE)     // 61696

// pre-converted W planes: [chunk][expert][pair] = uint2{plane1 bf16x2, plane2 bf16x2}
__device__ uint2 gWB[NCHUNK * NUM_EXPERTS * 16];

// ---------------------------------------------------------------------------
static __device__ __forceinline__ uint32_t bf16x2_rn(float lo, float hi) {
    uint32_t r;
    asm("cvt.rn.bf16x2.f32 %0, %1, %2;" : "=r"(r) : "f"(hi), "f"(lo));
    return r;
}
static __device__ __forceinline__ float bf16_lo_f(uint32_t u) {
    return __uint_as_float(u << 16);
}
static __device__ __forceinline__ float bf16_hi_f(uint32_t u) {
    return __uint_as_float(u & 0xffff0000u);
}
static __device__ __forceinline__ uint2 split_pair(float x, float y) {
    uint32_t b1 = bf16x2_rn(x, y);
    float r1x = x - bf16_lo_f(b1);
    float r1y = y - bf16_hi_f(b1);
    uint32_t b2 = bf16x2_rn(r1x, r1y);
    return make_uint2(b1, b2);
}
static __device__ __forceinline__ uint4 pack4(const float4& v) {
    uint2 p0 = split_pair(v.x, v.y);
    uint2 p1 = split_pair(v.z, v.w);
    return make_uint4(p0.x, p0.y, p1.x, p1.y);
}
static __device__ __forceinline__ uint2 lds_pair(const char* base, int row, int p) {
    return *(const uint2*)(base + row * ROWB + p * 8);
}
static __device__ __forceinline__ void mma_bf16(float* d,
                                                uint32_t a0, uint32_t a1,
                                                uint32_t a2, uint32_t a3,
                                                uint32_t b0, uint32_t b1) {
    asm volatile(
        "mma.sync.aligned.m16n8k16.row.col.f32.bf16.bf16.f32 "
        "{%0,%1,%2,%3}, {%4,%5,%6,%7}, {%8,%9}, {%0,%1,%2,%3};"
        : "+f"(d[0]), "+f"(d[1]), "+f"(d[2]), "+f"(d[3])
        : "r"(a0), "r"(a1), "r"(a2), "r"(a3), "r"(b0), "r"(b1));
}

#define BAR_ARRIVE(id) asm volatile("bar.arrive %0, %1;" :: "r"(id), "r"(THREADS) : "memory")
#define BAR_SYNCN(id)  asm volatile("bar.sync %0, %1;"   :: "r"(id), "r"(THREADS) : "memory")
#define CP_ASYNC16(d, s) asm volatile("cp.async.ca.shared.global [%0], [%1], 16;" \
                                      :: "r"(d), "l"(s) : "memory")
#define CP_COMMIT()    asm volatile("cp.async.commit_group;" ::: "memory")
#define CP_WAIT0()     asm volatile("cp.async.wait_group 0;" ::: "memory")

static __device__ __forceinline__ uint32_t smem_u32(const void* p) {
    uint32_t a;
    asm("{ .reg .u64 t; cvta.to.shared.u64 t, %1; cvt.u32.u64 %0, t; }"
        : "=r"(a) : "l"(p));
    return a;
}

// ---------------------------------------------------------------------------
// Kernel 0: convert W -> bf16 plane pairs in tile order (512 KB, L2-resident)
// ---------------------------------------------------------------------------
__global__ void conv_w(const float* __restrict__ W) {
    int pi = blockIdx.x * 256 + threadIdx.x;          // 0..16383, x4 strided
    #pragma unroll
    for (int it = 0; it < 4; it++, pi += 16384) {
        int p = pi & 15, e = (pi >> 4) & 63, c = pi >> 10;
        int k = c * BK + 2 * p;
        gWB[pi] = split_pair(W[e * D_MODEL + k], W[e * D_MODEL + k + 1]);
    }
}

// ---------------------------------------------------------------------------
// Kernel 1: warp-specialized bf16x3 GEMM + top-4 gap test + in-CTA fp64 refine
// ---------------------------------------------------------------------------
__global__ __launch_bounds__(THREADS)
void router_fused(const float* __restrict__ X, const float* __restrict__ W,
                  const float* __restrict__ bias, float* __restrict__ out) {
    extern __shared__ __align__(16) char smem[];
    float* bias_s = (float*)(smem + SM_BIAS);
    char*  bufs   = smem + SM_BUF;
    const uint32_t sm32_bufs = smem_u32(bufs);

    const int tid  = threadIdx.x;
    const int wid  = tid >> 5;
    const int lane = tid & 31;
    const int token0 = blockIdx.x * BM;

    if (tid < NUM_EXPERTS) bias_s[tid] = bias[tid];
    __syncthreads();

    float acc[2][4][4];
    #pragma unroll
    for (int m = 0; m < 2; m++)
        #pragma unroll
        for (int n = 0; n < 4; n++)
            #pragma unroll
            for (int r = 0; r < 4; r++) acc[m][n][r] = 0.0f;

    if (wid >= 4) {
        // ================= PRODUCERS (warps 4,5; 64 threads) ==============
        const int ptid = tid - 128;
        const int r  = ptid >> 3;       // 0..7 (row group)
        const int kq = ptid & 7;        // 0..7 (16B column)
        const int e  = ptid;            // expert row for cp.async

        float4 xa[8], xb[8];
        #pragma unroll
        for (int j = 0; j < 8; j++)
            xa[j] = *(const float4*)(X + (size_t)(token0 + r + 8 * j) * D_MODEL + kq * 4);

        #pragma unroll 1
        for (int c = 0; c < NCHUNK; c += 2) {
            // ---- chunk c (xa) ----
            {
                const int s = c % NSTAGE;
                char* st = bufs + s * STAGE;
                if (c >= NSTAGE) BAR_SYNCN(4 + s);
                // B tile via cp.async from pre-converted planes
                const char* src = (const char*)(gWB + ((size_t)c * NUM_EXPERTS + e) * 16);
                uint32_t dst = sm32_bufs + s * STAGE + BOFF + e * ROWB;
                #pragma unroll
                for (int i = 0; i < 8; i++) CP_ASYNC16(dst + i * 16, src + i * 16);
                CP_COMMIT();
                // A tile: convert + store
                #pragma unroll
                for (int j = 0; j < 8; j++)
                    *(uint4*)(st + (r + 8 * j) * ROWB + kq * 16) = pack4(xa[j]);
                // prefetch chunk c+1
                {
                    const int k0 = (c + 1) * BK;
                    #pragma unroll
                    for (int j = 0; j < 8; j++)
                        xb[j] = *(const float4*)(X + (size_t)(token0 + r + 8 * j) * D_MODEL + k0 + kq * 4);
                }
                CP_WAIT0();
                BAR_ARRIVE(1 + s);
            }
            // ---- chunk c+1 (xb) ----
            {
                const int c1 = c + 1;
                const int s = c1 % NSTAGE;
                char* st = bufs + s * STAGE;
                if (c1 >= NSTAGE) BAR_SYNCN(4 + s);
                const char* src = (const char*)(gWB + ((size_t)c1 * NUM_EXPERTS + e) * 16);
                uint32_t dst = sm32_bufs + s * STAGE + BOFF + e * ROWB;
                #pragma unroll
                for (int i = 0; i < 8; i++) CP_ASYNC16(dst + i * 16, src + i * 16);
                CP_COMMIT();
                #pragma unroll
                for (int j = 0; j < 8; j++)
                    *(uint4*)(st + (r + 8 * j) * ROWB + kq * 16) = pack4(xb[j]);
                if (c + 2 < NCHUNK) {
                    const int k0 = (c + 2) * BK;
                    #pragma unroll
                    for (int j = 0; j < 8; j++)
                        xa[j] = *(const float4*)(X + (size_t)(token0 + r + 8 * j) * D_MODEL + k0 + kq * 4);
                }
                CP_WAIT0();
                BAR_ARRIVE(1 + s);
            }
        }
    } else {
        // ================= CONSUMERS (warps 0-3; 128 threads) =============
        const int grp = lane >> 2;          // 0..7
        const int qid = lane & 3;           // 0..3
        const int rA  = (wid >> 1) * 32 + grp;   // token rows rA+16m, +8
        const int eb  = (wid & 1) * 32;          // expert half

        #pragma unroll 1
        for (int c = 0; c < NCHUNK; c++) {
            const int s = c % NSTAGE;
            BAR_SYNCN(1 + s);
            const char* As = bufs + s * STAGE;
            const char* Bs = As + BOFF;
            #pragma unroll
            for (int s8 = 0; s8 < 2; s8++) {
                const int p0 = s8 * 8 + qid;
                uint2 bf[4][2];
                #pragma unroll
                for (int n = 0; n < 4; n++) {
                    const int e = eb + n * 8 + grp;
                    bf[n][0] = lds_pair(Bs, e, p0);
                    bf[n][1] = lds_pair(Bs, e, p0 + 4);
                }
                uint2 af[2][4];
                #pragma unroll
                for (int m = 0; m < 2; m++) {
                    af[m][0] = lds_pair(As, rA + 16 * m,     p0);
                    af[m][1] = lds_pair(As, rA + 16 * m + 8, p0);
                    af[m][2] = lds_pair(As, rA + 16 * m,     p0 + 4);
                    af[m][3] = lds_pair(As, rA + 16 * m + 8, p0 + 4);
                }
                #pragma unroll
                for (int m = 0; m < 2; m++)
                    #pragma unroll
                    for (int n = 0; n < 4; n++) {
                        float* d = acc[m][n];
                        mma_bf16(d, af[m][0].x, af[m][1].x, af[m][2].x, af[m][3].x,
                                 bf[n][0].x, bf[n][1].x);                       // 1*1
                        mma_bf16(d, af[m][0].x, af[m][1].x, af[m][2].x, af[m][3].x,
                                 bf[n][0].y, bf[n][1].y);                       // 1*2
                        mma_bf16(d, af[m][0].y, af[m][1].y, af[m][2].y, af[m][3].y,
                                 bf[n][0].x, bf[n][1].x);                       // 2*1
                    }
            }
            BAR_ARRIVE(4 + s);
        }
    }
    __syncthreads();

    // ------------------------------------------------------------------
    // epilogue: stage logits, per-token top-4 scan, gap test
    // ------------------------------------------------------------------
    float* L     = (float*)(smem + SM_BUF);      // L[t][e] at t*LSTRIDE+e
    int*   flags = (int*)(smem + SM_FLAGS);

    if (wid < 4) {
        const int grp = lane >> 2, qid = lane & 3;
        const int rA  = (wid >> 1) * 32 + grp;
        const int eb  = (wid & 1) * 32;
        #pragma unroll
        for (int m = 0; m < 2; m++)
            #pragma unroll
            for (int n = 0; n < 4; n++) {
                int row = rA + 16 * m;
                int e0  = eb + n * 8 + 2 * qid;
                L[row * LSTRIDE + e0]           = acc[m][n][0];
                L[row * LSTRIDE + e0 + 1]       = acc[m][n][1];
                L[(row + 8) * LSTRIDE + e0]     = acc[m][n][2];
                L[(row + 8) * LSTRIDE + e0 + 1] = acc[m][n][3];
            }
    }
    if (tid == 0) flags[0] = 0;
    __syncthreads();

    if (tid < BM) {
        const float* Lr = L + tid * LSTRIDE;
        float tv0 = -1e30f, tv1 = -1e30f, tv2 = -1e30f, tv3 = -1e30f;
        int   ti0 = 0, ti1 = 0, ti2 = 0, ti3 = 0;
        #pragma unroll
        for (int e = 0; e < NUM_EXPERTS; e++) {
            float v = Lr[e] + bias_s[e];
            if (v > tv0) {
                tv3 = tv2; ti3 = ti2; tv2 = tv1; ti2 = ti1;
                tv1 = tv0; ti1 = ti0; tv0 = v;  ti0 = e;
            } else if (v > tv1) {
                tv3 = tv2; ti3 = ti2; tv2 = tv1; ti2 = ti1; tv1 = v; ti1 = e;
            } else if (v > tv2) {
                tv3 = tv2; ti3 = ti2; tv2 = v;  ti2 = e;
            } else if (v > tv3) {
                tv3 = v; ti3 = e;
            }
        }
        const int token = token0 + tid;
        if ((tv0 - tv1) < GAP_THRESH || (tv1 - tv2) < GAP_THRESH) {
            int idx = atomicAdd(&flags[0], 1);
            int* rec = &flags[1 + idx * 5];
            rec[0] = token; rec[1] = ti0; rec[2] = ti1; rec[3] = ti2; rec[4] = ti3;
        } else {
            float r  = expf(tv1 - tv0);
            out[token * 2 + 0] = 1.0f / (1.0f + r);
            out[token * 2 + 1] = r / (1.0f + r);
            out[N_TOKENS * 2 + token * 2 + 0] = (float)ti0;
            out[N_TOKENS * 2 + token * 2 + 1] = (float)ti1;
        }
    }
    __syncthreads();

    // ------------------------------------------------------------------
    // in-CTA fp64 refinement of flagged tokens (one warp per record)
    // ------------------------------------------------------------------
    const int nrec = flags[0];
    for (int r = wid; r < nrec; r += 6) {
        const int* rec = &flags[1 + r * 5];
        const int token = rec[0];
        const float* xr = X + (size_t)token * D_MODEL;
        const float* w0 = W + (size_t)rec[1] * D_MODEL;
        const float* w1 = W + (size_t)rec[2] * D_MODEL;
        const float* w2 = W + (size_t)rec[3] * D_MODEL;
        const float* w3 = W + (size_t)rec[4] * D_MODEL;

        double a0[4] = {0, 0, 0, 0}, a1[4] = {0, 0, 0, 0};
        #pragma unroll 4
        for (int k = lane; k < D_MODEL; k += 64) {
            double x0 = (double)xr[k], x1 = (double)xr[k + 32];
            a0[0] += x0 * (double)w0[k];  a1[0] += x1 * (double)w0[k + 32];
            a0[1] += x0 * (double)w1[k];  a1[1] += x1 * (double)w1[k + 32];
            a0[2] += x0 * (double)w2[k];  a1[2] += x1 * (double)w2[k + 32];
            a0[3] += x0 * (double)w3[k];  a1[3] += x1 * (double)w3[k + 32];
        }
        double lv[4];
        #pragma unroll
        for (int cc = 0; cc < 4; cc++) {
            double s = a0[cc] + a1[cc];
            #pragma unroll
            for (int off = 16; off; off >>= 1)
                s += __shfl_down_sync(0xffffffffu, s, off);
            lv[cc] = s + (double)bias_s[rec[1 + cc]];
        }
        if (lane == 0) {
            int ei[4] = {rec[1], rec[2], rec[3], rec[4]};
            #pragma unroll
            for (int i = 1; i < 4; i++) {
                double v = lv[i]; int id = ei[i];
                int j = i - 1;
                while (j >= 0 && (lv[j] < v || (lv[j] == v && ei[j] > id))) {
                    lv[j + 1] = lv[j]; ei[j + 1] = ei[j]; j--;
                }
                lv[j + 1] = v; ei[j + 1] = id;
            }
            double rr = exp(lv[1] - lv[0]);
            out[token * 2 + 0] = (float)(1.0 / (1.0 + rr));
            out[token * 2 + 1] = (float)(rr / (1.0 + rr));
            out[N_TOKENS * 2 + token * 2 + 0] = (float)ei[0];
            out[N_TOKENS * 2 + token * 2 + 1] = (float)ei[1];
        }
    }
}

// ---------------------------------------------------------------------------
extern "C" void kernel_launch(void* const* d_in, const int* in_sizes, int n_in,
                              void* d_out, int out_size) {
    const float* X = (const float*)d_in[0];   // [4, 4096, 2048]
    const float* W = (const float*)d_in[1];   // [64, 2048]
    const float* b = (const float*)d_in[2];   // [64]
    float* out = (float*)d_out;

    static int configured = 0;
    if (!configured) {
        cudaFuncSetAttribute(router_fused,
                             cudaFuncAttributeMaxDynamicSharedMemorySize, SMEM_TOTAL);
        configured = 1;
    }
    conv_w<<<64, 256>>>(W);
    router_fused<<<N_TOKENS / BM, THREADS, SMEM_TOTAL>>>(X, W, b, out);
}

// round 13
// speedup vs baseline: 1.0877x; 1.0877x over previous
#include <cuda_runtime.h>
#include <cstdint>
#include <math.h>

#define D_MODEL     2048
#define NUM_EXPERTS 64
#define N_TOKENS    16384
#define BM          64                  // tokens per CTA
#define BK          32                  // K per chunk
#define NCHUNK      (D_MODEL / BK)      // 64
#define THREADS     128                 // 4 warps; warp tile = 16 tokens x 64 experts
#define NSTAGE      4
#define ROWB        176                 // bytes per smem row (128 data + 48 pad; 4*11 floats)
#define GAP_THRESH  3e-4f
#define LSTRIDE     65

// stage = A-raw fp32 tile (64 x 176) then B-plane tile (64 x 176)
#define SM_BIAS     0
#define SM_BUF      256
#define BOFF        (BM * ROWB)                   // 11264
#define STAGEB      (2 * BOFF)                    // 22528
#define SM_FLAGS    (SM_BUF + 16640)              // after L[64][65] floats
#define SMEM_TOTAL  (SM_BUF + NSTAGE * STAGEB)    // 90368

// pre-converted W planes: [chunk][expert][pair] = uint2{plane1 bf16x2, plane2 bf16x2}
__device__ uint2 gWB[NCHUNK * NUM_EXPERTS * 16];

// ---------------------------------------------------------------------------
static __device__ __forceinline__ uint32_t bf16x2_rn(float lo, float hi) {
    uint32_t r;
    asm("cvt.rn.bf16x2.f32 %0, %1, %2;" : "=r"(r) : "f"(hi), "f"(lo));
    return r;
}
static __device__ __forceinline__ float bf16_lo_f(uint32_t u) {
    return __uint_as_float(u << 16);
}
static __device__ __forceinline__ float bf16_hi_f(uint32_t u) {
    return __uint_as_float(u & 0xffff0000u);
}
static __device__ __forceinline__ uint2 split_pair(float x, float y) {
    uint32_t b1 = bf16x2_rn(x, y);
    float r1x = x - bf16_lo_f(b1);
    float r1y = y - bf16_hi_f(b1);
    uint32_t b2 = bf16x2_rn(r1x, r1y);
    return make_uint2(b1, b2);
}
static __device__ __forceinline__ uint2 lds_pair(const char* base, int row, int p) {
    return *(const uint2*)(base + row * ROWB + p * 8);
}
static __device__ __forceinline__ uint2 lds_split(const char* base, int row, int p) {
    float2 v = *(const float2*)(base + row * ROWB + p * 8);
    return split_pair(v.x, v.y);
}
static __device__ __forceinline__ void mma_bf16(float* d,
                                                uint32_t a0, uint32_t a1,
                                                uint32_t a2, uint32_t a3,
                                                uint32_t b0, uint32_t b1) {
    asm volatile(
        "mma.sync.aligned.m16n8k16.row.col.f32.bf16.bf16.f32 "
        "{%0,%1,%2,%3}, {%4,%5,%6,%7}, {%8,%9}, {%0,%1,%2,%3};"
        : "+f"(d[0]), "+f"(d[1]), "+f"(d[2]), "+f"(d[3])
        : "r"(a0), "r"(a1), "r"(a2), "r"(a3), "r"(b0), "r"(b1));
}

#define CP_ASYNC16(dst, gsrc) \
    asm volatile("cp.async.cg.shared.global [%0], [%1], 16;" \
                 :: "r"(dst), "l"(gsrc) : "memory")
#define CP_COMMIT()  asm volatile("cp.async.commit_group;" ::: "memory")
#define CP_WAIT(n)   asm volatile("cp.async.wait_group %0;" :: "n"(n) : "memory")

static __device__ __forceinline__ uint32_t smem_u32(const void* p) {
    uint32_t a;
    asm("{ .reg .u64 t; cvta.to.shared.u64 t, %1; cvt.u32.u64 %0, t; }"
        : "=r"(a) : "l"(p));
    return a;
}

// ---------------------------------------------------------------------------
// Kernel 0: convert W -> bf16 plane pairs in [chunk][expert][pair] order
// ---------------------------------------------------------------------------
__global__ void conv_w(const float* __restrict__ W) {
    int pi = blockIdx.x * 256 + threadIdx.x;          // stride over 65536 pairs
    #pragma unroll
    for (int it = 0; it < 4; it++, pi += 16384) {
        int p = pi & 15, e = (pi >> 4) & 63, c = pi >> 10;
        int k = c * BK + 2 * p;
        gWB[pi] = split_pair(W[e * D_MODEL + k], W[e * D_MODEL + k + 1]);
    }
}

// ---------------------------------------------------------------------------
// Kernel 1: cp.async-pipelined bf16x3 GEMM + top-4 gap test + in-CTA fp64 refine
// ---------------------------------------------------------------------------
__global__ __launch_bounds__(THREADS)
void router_fused(const float* __restrict__ X, const float* __restrict__ W,
                  const float* __restrict__ bias, float* __restrict__ out) {
    extern __shared__ __align__(16) char smem[];
    float* bias_s = (float*)(smem + SM_BIAS);
    char*  bufs   = smem + SM_BUF;
    const uint32_t sbase = smem_u32(bufs);

    const int tid  = threadIdx.x;
    const int wid  = tid >> 5;
    const int lane = tid & 31;
    const int grp  = lane >> 2;     // 0..7
    const int qid  = lane & 3;      // 0..3
    const int token0 = blockIdx.x * BM;
    const int r0 = wid * 16 + grp;  // warp tile: rows r0, r0+8

    if (tid < NUM_EXPERTS) bias_s[tid] = bias[tid];

    // per-thread cp.async slots: 4 units A + 4 units B per chunk
    uint32_t smoff[4];
    unsigned long long gA[4], gB[4];
    #pragma unroll
    for (int j = 0; j < 4; j++) {
        int g = j * THREADS + tid;            // 0..511
        int row = g >> 3, u = g & 7;
        smoff[j] = (uint32_t)(row * ROWB + u * 16);
        gA[j] = (unsigned long long)__cvta_generic_to_global(
                    X + (size_t)(token0 + row) * D_MODEL + u * 4);
        gB[j] = (unsigned long long)__cvta_generic_to_global(
                    (const char*)gWB + (size_t)row * 128 + u * 16);
    }

    float acc[8][4];
    #pragma unroll
    for (int n = 0; n < 8; n++)
        #pragma unroll
        for (int r = 0; r < 4; r++) acc[n][r] = 0.0f;

    // prologue: issue chunks 0..2
    #pragma unroll
    for (int c = 0; c < 3; c++) {
        uint32_t st = sbase + c * STAGEB;
        #pragma unroll
        for (int j = 0; j < 4; j++)
            CP_ASYNC16(st + smoff[j], gA[j] + (size_t)c * 128);
        #pragma unroll
        for (int j = 0; j < 4; j++)
            CP_ASYNC16(st + BOFF + smoff[j], gB[j] + (size_t)c * 8192);
        CP_COMMIT();
    }

    #pragma unroll 1
    for (int c = 0; c < NCHUNK; c++) {
        CP_WAIT(2);            // group for chunk c complete
        __syncthreads();       // visibility across threads; stage (c-1)%4 free

        if (c + 3 < NCHUNK) {  // issue chunk c+3 into stage (c+3)&3
            const int cn = c + 3;
            uint32_t st = sbase + (cn & 3) * STAGEB;
            #pragma unroll
            for (int j = 0; j < 4; j++)
                CP_ASYNC16(st + smoff[j], gA[j] + (size_t)cn * 128);
            #pragma unroll
            for (int j = 0; j < 4; j++)
                CP_ASYNC16(st + BOFF + smoff[j], gB[j] + (size_t)cn * 8192);
        }
        CP_COMMIT();

        const char* As = bufs + (c & 3) * STAGEB;   // raw fp32
        const char* Bs = As + BOFF;                 // bf16 planes
        #pragma unroll
        for (int s8 = 0; s8 < 2; s8++) {
            const int p0 = s8 * 8 + qid;
            // A fragments: load fp32 pairs, split to planes in registers
            uint2 a0 = lds_split(As, r0,     p0);
            uint2 a1 = lds_split(As, r0 + 8, p0);
            uint2 a2 = lds_split(As, r0,     p0 + 4);
            uint2 a3 = lds_split(As, r0 + 8, p0 + 4);
            #pragma unroll
            for (int n = 0; n < 8; n++) {
                const int e = n * 8 + grp;
                uint2 b0 = lds_pair(Bs, e, p0);
                uint2 b1 = lds_pair(Bs, e, p0 + 4);
                mma_bf16(acc[n], a0.x, a1.x, a2.x, a3.x, b0.x, b1.x); // 1*1
                mma_bf16(acc[n], a0.x, a1.x, a2.x, a3.x, b0.y, b1.y); // 1*2
                mma_bf16(acc[n], a0.y, a1.y, a2.y, a3.y, b0.x, b1.x); // 2*1
            }
        }
    }
    CP_WAIT(0);
    __syncthreads();

    // ------------------------------------------------------------------
    // epilogue: stage logits, per-token top-4 scan, gap test
    // ------------------------------------------------------------------
    float* L     = (float*)(smem + SM_BUF);      // L[t][e] at t*LSTRIDE+e
    int*   flags = (int*)(smem + SM_FLAGS);

    #pragma unroll
    for (int n = 0; n < 8; n++) {
        int e0 = n * 8 + 2 * qid;
        L[r0 * LSTRIDE + e0]           = acc[n][0];
        L[r0 * LSTRIDE + e0 + 1]       = acc[n][1];
        L[(r0 + 8) * LSTRIDE + e0]     = acc[n][2];
        L[(r0 + 8) * LSTRIDE + e0 + 1] = acc[n][3];
    }
    if (tid == 0) flags[0] = 0;
    __syncthreads();

    if (tid < BM) {
        const float* Lr = L + tid * LSTRIDE;
        float tv0 = -1e30f, tv1 = -1e30f, tv2 = -1e30f, tv3 = -1e30f;
        int   ti0 = 0, ti1 = 0, ti2 = 0, ti3 = 0;
        #pragma unroll
        for (int e = 0; e < NUM_EXPERTS; e++) {
            float v = Lr[e] + bias_s[e];
            if (v > tv0) {
                tv3 = tv2; ti3 = ti2; tv2 = tv1; ti2 = ti1;
                tv1 = tv0; ti1 = ti0; tv0 = v;  ti0 = e;
            } else if (v > tv1) {
                tv3 = tv2; ti3 = ti2; tv2 = tv1; ti2 = ti1; tv1 = v; ti1 = e;
            } else if (v > tv2) {
                tv3 = tv2; ti3 = ti2; tv2 = v;  ti2 = e;
            } else if (v > tv3) {
                tv3 = v; ti3 = e;
            }
        }
        const int token = token0 + tid;
        if ((tv0 - tv1) < GAP_THRESH || (tv1 - tv2) < GAP_THRESH) {
            int idx = atomicAdd(&flags[0], 1);
            int* rec = &flags[1 + idx * 5];
            rec[0] = token; rec[1] = ti0; rec[2] = ti1; rec[3] = ti2; rec[4] = ti3;
        } else {
            float r  = expf(tv1 - tv0);
            out[token * 2 + 0] = 1.0f / (1.0f + r);
            out[token * 2 + 1] = r / (1.0f + r);
            out[N_TOKENS * 2 + token * 2 + 0] = (float)ti0;
            out[N_TOKENS * 2 + token * 2 + 1] = (float)ti1;
        }
    }
    __syncthreads();

    // ------------------------------------------------------------------
    // in-CTA fp64 refinement of flagged tokens (one warp per record)
    // ------------------------------------------------------------------
    const int nrec = flags[0];
    for (int r = wid; r < nrec; r += 4) {
        const int* rec = &flags[1 + r * 5];
        const int token = rec[0];
        const float* xr = X + (size_t)token * D_MODEL;
        const float* w0 = W + (size_t)rec[1] * D_MODEL;
        const float* w1 = W + (size_t)rec[2] * D_MODEL;
        const float* w2 = W + (size_t)rec[3] * D_MODEL;
        const float* w3 = W + (size_t)rec[4] * D_MODEL;

        double a0[4] = {0, 0, 0, 0}, a1[4] = {0, 0, 0, 0};
        #pragma unroll 4
        for (int k = lane; k < D_MODEL; k += 64) {
            double x0 = (double)xr[k], x1 = (double)xr[k + 32];
            a0[0] += x0 * (double)w0[k];  a1[0] += x1 * (double)w0[k + 32];
            a0[1] += x0 * (double)w1[k];  a1[1] += x1 * (double)w1[k + 32];
            a0[2] += x0 * (double)w2[k];  a1[2] += x1 * (double)w2[k + 32];
            a0[3] += x0 * (double)w3[k];  a1[3] += x1 * (double)w3[k + 32];
        }
        double lv[4];
        #pragma unroll
        for (int cc = 0; cc < 4; cc++) {
            double s = a0[cc] + a1[cc];
            #pragma unroll
            for (int off = 16; off; off >>= 1)
                s += __shfl_down_sync(0xffffffffu, s, off);
            lv[cc] = s + (double)bias_s[rec[1 + cc]];
        }
        if (lane == 0) {
            int ei[4] = {rec[1], rec[2], rec[3], rec[4]};
            #pragma unroll
            for (int i = 1; i < 4; i++) {
                double v = lv[i]; int id = ei[i];
                int j = i - 1;
                while (j >= 0 && (lv[j] < v || (lv[j] == v && ei[j] > id))) {
                    lv[j + 1] = lv[j]; ei[j + 1] = ei[j]; j--;
                }
                lv[j + 1] = v; ei[j + 1] = id;
            }
            double rr = exp(lv[1] - lv[0]);
            out[token * 2 + 0] = (float)(1.0 / (1.0 + rr));
            out[token * 2 + 1] = (float)(rr / (1.0 + rr));
            out[N_TOKENS * 2 + token * 2 + 0] = (float)ei[0];
            out[N_TOKENS * 2 + token * 2 + 1] = (float)ei[1];
        }
    }
}

// ---------------------------------------------------------------------------
extern "C" void kernel_launch(void* const* d_in, const int* in_sizes, int n_in,
                              void* d_out, int out_size) {
    const float* X = (const float*)d_in[0];   // [4, 4096, 2048]
    const float* W = (const float*)d_in[1];   // [64, 2048]
    const float* b = (const float*)d_in[2];   // [64]
    float* out = (float*)d_out;

    static int configured = 0;
    if (!configured) {
        cudaFuncSetAttribute(router_fused,
                             cudaFuncAttributeMaxDynamicSharedMemorySize, SMEM_TOTAL);
        configured = 1;
    }
    conv_w<<<64, 256>>>(W);
    router_fused<<<N_TOKENS / BM, THREADS, SMEM_TOTAL>>>(X, W, b, out);
}